// round 4
// baseline (speedup 1.0000x reference)
#include <cuda_runtime.h>
#include <cuda_fp16.h>
#include <math.h>
#include <stdint.h>

#define N 8192
#define C 256
#define KA 512            // A expanded: [hi | lo] fp16
#define TM 256            // CTA M tile
#define TN 128            // CTA N tile
#define KC 64             // K chunk (64 halves = 128B rows)
#define NCHUNK (KA / KC)  // 8
#define NTHREADS 512
#define A_STAGE 32768     // one A stage: 256 rows x 128B
#define NSTAGE 3
#define B_OFF (NSTAGE * A_STAGE)      // 98304
#define SMEM_BYTES (B_OFF + 65536 + 1024)
#define EPS 6.0e-4f
#define PAIR_CAP (8u * 1024u * 1024u)

// ---------------- scratch (device globals; no allocation allowed) -----------
__device__ __half g_ae1[(size_t)N * KA];   // v1: [hi|lo]
__device__ __half g_ae2[(size_t)N * KA];   // v2: [hi|lo]
__device__ __half g_bh1[(size_t)N * C];    // p1 hi
__device__ __half g_bh2[(size_t)N * C];    // p2 hi
__device__ float g_yv1[(size_t)N * C];     // fp32 normalized (for repair)
__device__ float g_yv2[(size_t)N * C];
__device__ float g_yp1[(size_t)N * C];
__device__ float g_yp2[(size_t)N * C];
__device__ float g_diag1[N];
__device__ float g_diag2[N];
__device__ int   g_cnt1[N];
__device__ int   g_cnt2[N];
__device__ unsigned int g_np;
__device__ uint32_t g_pairs[PAIR_CAP];

// ---------------- helpers ----------------------------------------------------
__device__ __forceinline__ uint32_t smem_u32(const void* p) {
    uint32_t a;
    asm("{ .reg .u64 t; cvta.to.shared.u64 t, %1; cvt.u32.u64 %0, t; }" : "=r"(a) : "l"(p));
    return a;
}
#define SWZ(x) ((x) ^ (((x) >> 3) & 0x70))

__device__ __forceinline__ void cp_async16(uint32_t sa, const void* g) {
    asm volatile("cp.async.cg.shared.global [%0], [%1], 16;" :: "r"(sa), "l"(g));
}
__device__ __forceinline__ void ldsm_x4(uint32_t* r, uint32_t addr) {
    asm volatile("ldmatrix.sync.aligned.m8n8.x4.shared.b16 {%0,%1,%2,%3}, [%4];"
                 : "=r"(r[0]), "=r"(r[1]), "=r"(r[2]), "=r"(r[3]) : "r"(addr));
}
__device__ __forceinline__ void mma16816(float* d, const uint32_t* a, const uint32_t* b) {
    asm volatile("mma.sync.aligned.m16n8k16.row.col.f32.f16.f16.f32 "
                 "{%0,%1,%2,%3}, {%4,%5,%6,%7}, {%8,%9}, {%0,%1,%2,%3};"
                 : "+f"(d[0]), "+f"(d[1]), "+f"(d[2]), "+f"(d[3])
                 : "r"(a[0]), "r"(a[1]), "r"(a[2]), "r"(a[3]), "r"(b[0]), "r"(b[1]));
}

// ---------------- block reduce (256 threads) --------------------------------
__device__ __forceinline__ float blockReduceSum256(float v, float* sred) {
    #pragma unroll
    for (int o = 16; o; o >>= 1) v += __shfl_xor_sync(0xffffffffu, v, o);
    int lane = threadIdx.x & 31, w = threadIdx.x >> 5;
    if (lane == 0) sred[w] = v;
    __syncthreads();
    if (w == 0) {
        v = (lane < 8) ? sred[lane] : 0.0f;
        #pragma unroll
        for (int o = 4; o; o >>= 1) v += __shfl_xor_sync(0xffffffffu, v, o);
        if (lane == 0) sred[0] = v;
    }
    __syncthreads();
    float r = sred[0];
    __syncthreads();
    return r;
}

// ---------------- kernel 1: normalize + splits + diagonal dots --------------
__global__ __launch_bounds__(256) void normalize_kernel(
    const float* __restrict__ v1, const float* __restrict__ v2,
    const float* __restrict__ p1, const float* __restrict__ p2)
{
    __shared__ float sred[8];
    int row = blockIdx.x;
    int t = threadIdx.x;
    size_t off = (size_t)row * C + t;

    float a = v1[off], b = v2[off], c = p1[off], d = p2[off];

    float na = blockReduceSum256(a * a, sred);
    float nb = blockReduceSum256(b * b, sred);
    float nc = blockReduceSum256(c * c, sred);
    float nd = blockReduceSum256(d * d, sred);

    float ia = 1.0f / fmaxf(sqrtf(na), 1e-12f);
    float ib = 1.0f / fmaxf(sqrtf(nb), 1e-12f);
    float ic = 1.0f / fmaxf(sqrtf(nc), 1e-12f);
    float id = 1.0f / fmaxf(sqrtf(nd), 1e-12f);

    float an = a * ia, bn = b * ib, cn = c * ic, dn = d * id;

    g_yv1[off] = an; g_yv2[off] = bn; g_yp1[off] = cn; g_yp2[off] = dn;

    size_t eb = (size_t)row * KA + t;
    {   // A-side expanded [hi | lo]
        __half h = __float2half_rn(an);
        __half l = __float2half_rn(an - __half2float(h));
        g_ae1[eb] = h; g_ae1[eb + 256] = l;
        h = __float2half_rn(bn);
        l = __float2half_rn(bn - __half2float(h));
        g_ae2[eb] = h; g_ae2[eb + 256] = l;
    }
    // B-side hi only
    g_bh1[off] = __float2half_rn(cn);
    g_bh2[off] = __float2half_rn(dn);

    float d1 = blockReduceSum256(an * dn, sred);   // v1n . p2n
    float d2 = blockReduceSum256(bn * cn, sred);   // v2n . p1n

    if (t == 0) {
        g_diag1[row] = d1;
        g_diag2[row] = d2;
        g_cnt1[row] = 0;
        g_cnt2[row] = 0;
        if (row == 0) g_np = 0;
    }
}

// ---------------- kernel 2: mma.sync GEMM + classify (count / uncertain) ----
// CTA: 256x128 tile, 512 threads (16 warps, 4M x 4N), warp tile 64x32.
// A: K=512 in 8 chunks of 64 halves, 3-stage cp.async pipeline.
// B: 128 rows x 256 halves loaded ONCE into smem (4 sub-chunks; chunk c uses c&3).
extern __shared__ char dynsmem[];

__global__ void __launch_bounds__(NTHREADS, 1) count_kernel()
{
    __shared__ int scnt[TM];

    const __half* __restrict__ A;
    const __half* __restrict__ B;
    const float* __restrict__ diag;
    int* cnt;
    if (blockIdx.z == 0) { A = g_ae1; B = g_bh2; diag = g_diag1; cnt = g_cnt1; }
    else                 { A = g_ae2; B = g_bh1; diag = g_diag2; cnt = g_cnt2; }

    int tid = threadIdx.x;
    int wid = tid >> 5;
    int lane = tid & 31;
    int wm = wid >> 2;            // 0..3
    int wn = wid & 3;             // 0..3
    int row0 = blockIdx.y * TM;
    int col0 = blockIdx.x * TN;

    char* al = (char*)((((uintptr_t)dynsmem) + 1023) & ~(uintptr_t)1023);
    uint32_t sbase = smem_u32(al);

    if (tid < TM) scnt[tid] = 0;

    auto load_A = [&](int c, int s) {
        uint32_t st = sbase + (uint32_t)s * A_STAGE;
        #pragma unroll
        for (int i = 0; i < 4; i++) {            // 2048 x 16B
            int idx = tid + i * NTHREADS;
            int r = idx >> 3, kg = idx & 7;
            const __half* g = A + (size_t)(row0 + r) * KA + c * KC + kg * 8;
            cp_async16(st + SWZ((uint32_t)(r * 128 + kg * 16)), g);
        }
        asm volatile("cp.async.commit_group;" ::: "memory");
    };

    // B: all 4 sub-chunks (128 rows x 64 halves each), one group
    {
        #pragma unroll
        for (int i = 0; i < 8; i++) {            // 4096 x 16B
            int idx = tid + i * NTHREADS;
            int cb = idx >> 10;
            int rem = idx & 1023;
            int r = rem >> 3, kg = rem & 7;
            const __half* g = B + (size_t)(col0 + r) * C + cb * KC + kg * 8;
            cp_async16(sbase + B_OFF + (uint32_t)cb * 16384u +
                       SWZ((uint32_t)(r * 128 + kg * 16)), g);
        }
        asm volatile("cp.async.commit_group;" ::: "memory");
    }

    float acc[4][4][4];
    #pragma unroll
    for (int mi = 0; mi < 4; mi++)
        #pragma unroll
        for (int n8 = 0; n8 < 4; n8++)
            #pragma unroll
            for (int e = 0; e < 4; e++) acc[mi][n8][e] = 0.0f;

    load_A(0, 0);
    load_A(1, 1);

    for (int c = 0; c < NCHUNK; c++) {
        if (c + 2 < NCHUNK) {
            load_A(c + 2, (c + 2) % NSTAGE);
            asm volatile("cp.async.wait_group 2;" ::: "memory");
        } else if (c + 1 < NCHUNK) {
            asm volatile("cp.async.wait_group 1;" ::: "memory");
        } else {
            asm volatile("cp.async.wait_group 0;" ::: "memory");
        }
        __syncthreads();

        uint32_t stA = sbase + (uint32_t)(c % NSTAGE) * A_STAGE;
        uint32_t stB = sbase + B_OFF + (uint32_t)(c & 3) * 16384u;

        #pragma unroll
        for (int ks = 0; ks < 4; ks++) {         // k16 steps within chunk
            uint32_t a[4][4], b[2][4];
            int kbA = ks * 32 + (lane >> 4) * 16;
            #pragma unroll
            for (int mi = 0; mi < 4; mi++) {
                int rowA = wm * 64 + mi * 16 + (lane & 15);
                uint32_t ad = stA + (uint32_t)(rowA * 128) +
                              (uint32_t)(kbA ^ ((rowA & 7) << 4));
                ldsm_x4(a[mi], ad);
            }
            int kbB = ks * 32 + ((lane >> 3) & 1) * 16;
            #pragma unroll
            for (int nb = 0; nb < 2; nb++) {
                int rowB = wn * 32 + nb * 16 + (lane & 7) + ((lane >> 4) & 1) * 8;
                uint32_t bd = stB + (uint32_t)(rowB * 128) +
                              (uint32_t)(kbB ^ ((rowB & 7) << 4));
                ldsm_x4(b[nb], bd);
            }
            #pragma unroll
            for (int mi = 0; mi < 4; mi++)
                #pragma unroll
                for (int n8 = 0; n8 < 4; n8++)
                    mma16816(acc[mi][n8], a[mi], &b[n8 >> 1][(n8 & 1) * 2]);
        }
        __syncthreads();
    }

    // ---- epilogue: definite counts + uncertain collection ------------------
    int gid = lane >> 2, tig = lane & 3;
    int nu = 0;
    #pragma unroll
    for (int mi = 0; mi < 4; mi++) {
        #pragma unroll
        for (int h = 0; h < 2; h++) {
            int lrow = wm * 64 + mi * 16 + gid + h * 8;
            int grow = row0 + lrow;
            float dv = __ldg(&diag[grow]);
            int cc = 0;
            #pragma unroll
            for (int n8 = 0; n8 < 4; n8++) {
                #pragma unroll
                for (int e = 0; e < 2; e++) {
                    float vv = acc[mi][n8][h * 2 + e];
                    int gcol = col0 + wn * 32 + n8 * 8 + tig * 2 + e;
                    if (gcol != grow) {
                        if (vv > dv + EPS) cc++;
                        else if (vv > dv - EPS) nu++;
                    }
                }
            }
            if (cc) atomicAdd(&scnt[lrow], cc);
        }
    }

    // warp-aggregated append of uncertain pairs
    {
        unsigned mask = 0xffffffffu;
        int pre = nu;
        #pragma unroll
        for (int o = 1; o < 32; o <<= 1) {
            int v = __shfl_up_sync(mask, pre, o);
            if (lane >= o) pre += v;
        }
        int total = __shfl_sync(mask, pre, 31);
        unsigned base = 0;
        if (total > 0) {
            if (lane == 31) base = atomicAdd(&g_np, (unsigned)total);
            base = __shfl_sync(mask, base, 31);
            unsigned idx = base + (unsigned)(pre - nu);
            uint32_t dirbit = (uint32_t)blockIdx.z << 26;
            #pragma unroll
            for (int mi = 0; mi < 4; mi++) {
                #pragma unroll
                for (int h = 0; h < 2; h++) {
                    int lrow = wm * 64 + mi * 16 + gid + h * 8;
                    int grow = row0 + lrow;
                    float dv = __ldg(&diag[grow]);
                    #pragma unroll
                    for (int n8 = 0; n8 < 4; n8++) {
                        #pragma unroll
                        for (int e = 0; e < 2; e++) {
                            float vv = acc[mi][n8][h * 2 + e];
                            int gcol = col0 + wn * 32 + n8 * 8 + tig * 2 + e;
                            if (gcol != grow && vv <= dv + EPS && vv > dv - EPS) {
                                if (idx < PAIR_CAP)
                                    g_pairs[idx] = dirbit | ((uint32_t)grow << 13) | (uint32_t)gcol;
                                idx++;
                            }
                        }
                    }
                }
            }
        }
    }

    __syncthreads();
    if (tid < TM) {
        int v = scnt[tid];
        if (v) atomicAdd(&cnt[row0 + tid], v);
    }
}

// ---------------- kernel 3: exact fp32 repair of uncertain pairs ------------
__global__ __launch_bounds__(256) void repair_kernel()
{
    int gw = (blockIdx.x * blockDim.x + threadIdx.x) >> 5;
    int lane = threadIdx.x & 31;
    int nwarps = (gridDim.x * blockDim.x) >> 5;
    unsigned np = g_np;
    if (np > PAIR_CAP) np = PAIR_CAP;

    for (unsigned i = gw; i < np; i += nwarps) {
        uint32_t e = g_pairs[i];
        int dir = (int)(e >> 26);
        int row = (int)((e >> 13) & 8191u);
        int col = (int)(e & 8191u);
        const float* ya = dir ? g_yv2 : g_yv1;
        const float* yb = dir ? g_yp1 : g_yp2;
        const float* dg = dir ? g_diag2 : g_diag1;
        int* cnt = dir ? g_cnt2 : g_cnt1;

        const float4* ra = (const float4*)(ya + (size_t)row * C);
        const float4* rb = (const float4*)(yb + (size_t)col * C);
        float s = 0.0f;
        #pragma unroll
        for (int j = 0; j < 2; j++) {
            float4 a = ra[lane + j * 32];
            float4 b = rb[lane + j * 32];
            s = fmaf(a.x, b.x, fmaf(a.y, b.y, fmaf(a.z, b.z, fmaf(a.w, b.w, s))));
        }
        #pragma unroll
        for (int o = 16; o; o >>= 1) s += __shfl_xor_sync(0xffffffffu, s, o);
        if (lane == 0 && s > __ldg(&dg[row])) atomicAdd(&cnt[row], 1);
    }
}

// ---------------- kernel 4: final scalars ------------------------------------
__global__ __launch_bounds__(256) void finalize_kernel(float* __restrict__ out)
{
    int tid = threadIdx.x;
    double sd = 0.0, spos = 0.0;
    int r1 = 0, r5 = 0, r10 = 0;
    for (int i = tid; i < N; i += 256) {
        sd += (double)g_diag1[i] + (double)g_diag2[i];
        int c1 = g_cnt1[i], c2 = g_cnt2[i];
        spos += (double)(c1 + c2);
        r1  += (c1 < 1)  + (c2 < 1);
        r5  += (c1 < 5)  + (c2 < 5);
        r10 += (c1 < 10) + (c2 < 10);
    }
    #pragma unroll
    for (int o = 16; o; o >>= 1) {
        sd   += __shfl_xor_sync(0xffffffffu, sd, o);
        spos += __shfl_xor_sync(0xffffffffu, spos, o);
        r1   += __shfl_xor_sync(0xffffffffu, r1, o);
        r5   += __shfl_xor_sync(0xffffffffu, r5, o);
        r10  += __shfl_xor_sync(0xffffffffu, r10, o);
    }
    __shared__ double s_sd[8], s_sp[8];
    __shared__ int s_r1[8], s_r5[8], s_r10[8];
    int lane = tid & 31, w = tid >> 5;
    if (lane == 0) { s_sd[w] = sd; s_sp[w] = spos; s_r1[w] = r1; s_r5[w] = r5; s_r10[w] = r10; }
    __syncthreads();
    if (tid == 0) {
        double tsd = 0, tsp = 0; int t1 = 0, t5 = 0, t10 = 0;
        for (int i = 0; i < 8; i++) {
            tsd += s_sd[i]; tsp += s_sp[i];
            t1 += s_r1[i]; t5 += s_r5[i]; t10 += s_r10[i];
        }
        double inv2N = 1.0 / (2.0 * (double)N);
        out[0] = (float)(-tsd * inv2N);
        out[1] = (float)((double)t1  * inv2N);
        out[2] = (float)((double)t5  * inv2N);
        out[3] = (float)((double)t10 * inv2N);
        out[4] = (float)((tsp + (double)N) * inv2N);
    }
}

// ---------------- launch ------------------------------------------------------
extern "C" void kernel_launch(void* const* d_in, const int* in_sizes, int n_in,
                              void* d_out, int out_size)
{
    const float* v1 = (const float*)d_in[0];
    const float* v2 = (const float*)d_in[1];
    const float* p1 = (const float*)d_in[2];
    const float* p2 = (const float*)d_in[3];
    float* out = (float*)d_out;

    cudaFuncSetAttribute(count_kernel, cudaFuncAttributeMaxDynamicSharedMemorySize, SMEM_BYTES);

    normalize_kernel<<<N, 256>>>(v1, v2, p1, p2);
    dim3 grid(N / TN, N / TM, 2);
    count_kernel<<<grid, NTHREADS, SMEM_BYTES>>>();
    repair_kernel<<<1024, 256>>>();
    finalize_kernel<<<1, 256>>>(out);
}

// round 5
// speedup vs baseline: 1.3703x; 1.3703x over previous
#include <cuda_runtime.h>
#include <cuda_fp16.h>
#include <math.h>
#include <stdint.h>

#define N 8192
#define C 256
#define TM 256            // CTA M tile
#define TN 128            // CTA N tile
#define KC 64             // K chunk (64 halves = 128B rows)
#define NCHUNK 4          // K = 256
#define NTHREADS 512
#define A_STAGE 32768     // 256 rows x 128B
#define B_OFF (NCHUNK * A_STAGE)          // 131072
#define SMEM_BYTES (B_OFF + 65536 + 1024) // 197632
#define PAIR_CAP (4u * 1024u * 1024u)
#define SCAP 2048

// ---------------- scratch (device globals; no allocation allowed) -----------
__device__ __half g_ah1[(size_t)N * C];    // v1 hi
__device__ __half g_ah2[(size_t)N * C];    // v2 hi
__device__ __half g_bh1[(size_t)N * C];    // p1 hi
__device__ __half g_bh2[(size_t)N * C];    // p2 hi
__device__ float g_yv1[(size_t)N * C];     // fp32 normalized (repair)
__device__ float g_yv2[(size_t)N * C];
__device__ float g_yp1[(size_t)N * C];
__device__ float g_yp2[(size_t)N * C];
__device__ float g_nlv1[N], g_nlv2[N], g_nlp1[N], g_nlp2[N];  // ||lo|| per row
__device__ float g_diag1[N], g_diag2[N];
__device__ int   g_cnt1[N], g_cnt2[N];
__device__ unsigned int g_np;
__device__ uint32_t g_pairs[PAIR_CAP];
// finalize accumulators
__device__ double g_sd, g_sp;
__device__ int g_r1, g_r5, g_r10;
__device__ unsigned int g_ticket;

// ---------------- helpers ----------------------------------------------------
__device__ __forceinline__ uint32_t smem_u32(const void* p) {
    uint32_t a;
    asm("{ .reg .u64 t; cvta.to.shared.u64 t, %1; cvt.u32.u64 %0, t; }" : "=r"(a) : "l"(p));
    return a;
}
#define SWZ(x) ((x) ^ (((x) >> 3) & 0x70))

__device__ __forceinline__ void cp_async16(uint32_t sa, const void* g) {
    asm volatile("cp.async.cg.shared.global [%0], [%1], 16;" :: "r"(sa), "l"(g));
}
__device__ __forceinline__ void ldsm_x4(uint32_t* r, uint32_t addr) {
    asm volatile("ldmatrix.sync.aligned.m8n8.x4.shared.b16 {%0,%1,%2,%3}, [%4];"
                 : "=r"(r[0]), "=r"(r[1]), "=r"(r[2]), "=r"(r[3]) : "r"(addr));
}
__device__ __forceinline__ void mma16816(float* d, const uint32_t* a, const uint32_t* b) {
    asm volatile("mma.sync.aligned.m16n8k16.row.col.f32.f16.f16.f32 "
                 "{%0,%1,%2,%3}, {%4,%5,%6,%7}, {%8,%9}, {%0,%1,%2,%3};"
                 : "+f"(d[0]), "+f"(d[1]), "+f"(d[2]), "+f"(d[3])
                 : "r"(a[0]), "r"(a[1]), "r"(a[2]), "r"(a[3]), "r"(b[0]), "r"(b[1]));
}

// ---------------- block reduce (256 threads) --------------------------------
__device__ __forceinline__ float blockReduceSum256(float v, float* sred) {
    #pragma unroll
    for (int o = 16; o; o >>= 1) v += __shfl_xor_sync(0xffffffffu, v, o);
    int lane = threadIdx.x & 31, w = threadIdx.x >> 5;
    if (lane == 0) sred[w] = v;
    __syncthreads();
    if (w == 0) {
        v = (lane < 8) ? sred[lane] : 0.0f;
        #pragma unroll
        for (int o = 4; o; o >>= 1) v += __shfl_xor_sync(0xffffffffu, v, o);
        if (lane == 0) sred[0] = v;
    }
    __syncthreads();
    float r = sred[0];
    __syncthreads();
    return r;
}

// ---------------- kernel 1: normalize + hi split + lo-norms + diag ----------
__global__ __launch_bounds__(256) void normalize_kernel(
    const float* __restrict__ v1, const float* __restrict__ v2,
    const float* __restrict__ p1, const float* __restrict__ p2)
{
    __shared__ float sred[8];
    int row = blockIdx.x;
    int t = threadIdx.x;
    size_t off = (size_t)row * C + t;

    float a = v1[off], b = v2[off], c = p1[off], d = p2[off];

    float na = blockReduceSum256(a * a, sred);
    float nb = blockReduceSum256(b * b, sred);
    float nc = blockReduceSum256(c * c, sred);
    float nd = blockReduceSum256(d * d, sred);

    float ia = 1.0f / fmaxf(sqrtf(na), 1e-12f);
    float ib = 1.0f / fmaxf(sqrtf(nb), 1e-12f);
    float ic = 1.0f / fmaxf(sqrtf(nc), 1e-12f);
    float id = 1.0f / fmaxf(sqrtf(nd), 1e-12f);

    float an = a * ia, bn = b * ib, cn = c * ic, dn = d * id;
    g_yv1[off] = an; g_yv2[off] = bn; g_yp1[off] = cn; g_yp2[off] = dn;

    __half ha = __float2half_rn(an), hb = __float2half_rn(bn);
    __half hc = __float2half_rn(cn), hd = __float2half_rn(dn);
    g_ah1[off] = ha; g_ah2[off] = hb; g_bh1[off] = hc; g_bh2[off] = hd;

    float la = an - __half2float(ha), lb = bn - __half2float(hb);
    float lc = cn - __half2float(hc), ld = dn - __half2float(hd);

    float sla = blockReduceSum256(la * la, sred);
    float slb = blockReduceSum256(lb * lb, sred);
    float slc = blockReduceSum256(lc * lc, sred);
    float sld = blockReduceSum256(ld * ld, sred);

    float d1 = blockReduceSum256(an * dn, sred);   // v1n . p2n
    float d2 = blockReduceSum256(bn * cn, sred);   // v2n . p1n

    if (t == 0) {
        g_nlv1[row] = sqrtf(sla); g_nlv2[row] = sqrtf(slb);
        g_nlp1[row] = sqrtf(slc); g_nlp2[row] = sqrtf(sld);
        g_diag1[row] = d1; g_diag2[row] = d2;
        g_cnt1[row] = 0;  g_cnt2[row] = 0;
        if (row == 0) {
            g_np = 0; g_sd = 0.0; g_sp = 0.0;
            g_r1 = 0; g_r5 = 0; g_r10 = 0; g_ticket = 0;
        }
    }
}

// ---------------- kernel 2: hi-only mma.sync GEMM + classify ----------------
// CTA: 256x128 tile, 512 threads (16 warps 4x4), warp tile 64x32, K=256.
// All 4 A chunks + B loaded via cp.async in 5 commit groups; compute pipelined.
extern __shared__ char dynsmem[];

__global__ void __launch_bounds__(NTHREADS, 1) count_kernel()
{
    __shared__ int scnt[TM];
    __shared__ uint32_t s_pairs[SCAP];
    __shared__ unsigned int s_nu, s_base;

    const __half* __restrict__ A;
    const __half* __restrict__ B;
    const float* __restrict__ diag;
    const float* __restrict__ nla;
    const float* __restrict__ nlb;
    int* cnt;
    if (blockIdx.z == 0) { A = g_ah1; B = g_bh2; diag = g_diag1; nla = g_nlv1; nlb = g_nlp2; cnt = g_cnt1; }
    else                 { A = g_ah2; B = g_bh1; diag = g_diag2; nla = g_nlv2; nlb = g_nlp1; cnt = g_cnt2; }

    int tid = threadIdx.x;
    int wid = tid >> 5;
    int lane = tid & 31;
    int wm = wid >> 2;            // 0..3
    int wn = wid & 3;             // 0..3
    int row0 = blockIdx.y * TM;
    int col0 = blockIdx.x * TN;

    char* al = (char*)((((uintptr_t)dynsmem) + 1023) & ~(uintptr_t)1023);
    uint32_t sbase = smem_u32(al);

    if (tid < TM) scnt[tid] = 0;
    if (tid == 0) s_nu = 0;

    // B first (needed for chunk 0): 128 rows x 256 halves, 4 sub-chunks
    {
        #pragma unroll
        for (int i = 0; i < 8; i++) {            // 4096 x 16B
            int idx = tid + i * NTHREADS;
            int cb = idx >> 10;
            int rem = idx & 1023;
            int r = rem >> 3, kg = rem & 7;
            const __half* g = B + (size_t)(col0 + r) * C + cb * KC + kg * 8;
            cp_async16(sbase + B_OFF + (uint32_t)cb * 16384u +
                       SWZ((uint32_t)(r * 128 + kg * 16)), g);
        }
        asm volatile("cp.async.commit_group;" ::: "memory");
    }
    // A chunks 0..3, one group each
    #pragma unroll
    for (int c = 0; c < NCHUNK; c++) {
        uint32_t st = sbase + (uint32_t)c * A_STAGE;
        #pragma unroll
        for (int i = 0; i < 4; i++) {            // 2048 x 16B
            int idx = tid + i * NTHREADS;
            int r = idx >> 3, kg = idx & 7;
            const __half* g = A + (size_t)(row0 + r) * C + c * KC + kg * 8;
            cp_async16(st + SWZ((uint32_t)(r * 128 + kg * 16)), g);
        }
        asm volatile("cp.async.commit_group;" ::: "memory");
    }

    float acc[4][4][4];
    #pragma unroll
    for (int mi = 0; mi < 4; mi++)
        #pragma unroll
        for (int n8 = 0; n8 < 4; n8++)
            #pragma unroll
            for (int e = 0; e < 4; e++) acc[mi][n8][e] = 0.0f;

    #pragma unroll
    for (int c = 0; c < NCHUNK; c++) {
        if (c == 0)      asm volatile("cp.async.wait_group 3;" ::: "memory");
        else if (c == 1) asm volatile("cp.async.wait_group 2;" ::: "memory");
        else if (c == 2) asm volatile("cp.async.wait_group 1;" ::: "memory");
        else             asm volatile("cp.async.wait_group 0;" ::: "memory");
        __syncthreads();

        uint32_t stA = sbase + (uint32_t)c * A_STAGE;
        uint32_t stB = sbase + B_OFF + (uint32_t)c * 16384u;

        #pragma unroll
        for (int ks = 0; ks < 4; ks++) {
            uint32_t a[4][4], b[2][4];
            int kbA = ks * 32 + (lane >> 4) * 16;
            #pragma unroll
            for (int mi = 0; mi < 4; mi++) {
                int rowA = wm * 64 + mi * 16 + (lane & 15);
                uint32_t ad = stA + (uint32_t)(rowA * 128) +
                              (uint32_t)(kbA ^ ((rowA & 7) << 4));
                ldsm_x4(a[mi], ad);
            }
            int kbB = ks * 32 + ((lane >> 3) & 1) * 16;
            #pragma unroll
            for (int nb = 0; nb < 2; nb++) {
                int rowB = wn * 32 + nb * 16 + (lane & 7) + ((lane >> 4) & 1) * 8;
                uint32_t bd = stB + (uint32_t)(rowB * 128) +
                              (uint32_t)(kbB ^ ((rowB & 7) << 4));
                ldsm_x4(b[nb], bd);
            }
            #pragma unroll
            for (int mi = 0; mi < 4; mi++)
                #pragma unroll
                for (int n8 = 0; n8 < 4; n8++)
                    mma16816(acc[mi][n8], a[mi], &b[n8 >> 1][(n8 & 1) * 2]);
        }
    }

    // ---- epilogue: definite counts + uncertain via per-pair adaptive bound -
    int gid = lane >> 2, tig = lane & 3;
    uint32_t dirbit = (uint32_t)blockIdx.z << 26;

    float bcol[8];
    #pragma unroll
    for (int n8 = 0; n8 < 4; n8++)
        #pragma unroll
        for (int e = 0; e < 2; e++)
            bcol[n8 * 2 + e] = __ldg(&nlb[col0 + wn * 32 + n8 * 8 + tig * 2 + e]);

    #pragma unroll
    for (int mi = 0; mi < 4; mi++) {
        #pragma unroll
        for (int h = 0; h < 2; h++) {
            int lrow = wm * 64 + mi * 16 + gid + h * 8;
            int grow = row0 + lrow;
            float dv = __ldg(&diag[grow]);
            float na = __ldg(&nla[grow]);
            int cc = 0;
            #pragma unroll
            for (int n8 = 0; n8 < 4; n8++) {
                #pragma unroll
                for (int e = 0; e < 2; e++) {
                    float vv = acc[mi][n8][h * 2 + e];
                    int gcol = col0 + wn * 32 + n8 * 8 + tig * 2 + e;
                    float bnd = 0.375f * (na + bcol[n8 * 2 + e]) + 4e-5f;
                    if (gcol != grow) {
                        if (vv > dv + bnd) cc++;
                        else if (vv > dv - bnd) {
                            unsigned idx = atomicAdd(&s_nu, 1u);
                            uint32_t rec = dirbit | ((uint32_t)grow << 13) | (uint32_t)gcol;
                            if (idx < SCAP) s_pairs[idx] = rec;
                            else {
                                unsigned gi = atomicAdd(&g_np, 1u);
                                if (gi < PAIR_CAP) g_pairs[gi] = rec;
                            }
                        }
                    }
                }
            }
            if (cc) atomicAdd(&scnt[lrow], cc);
        }
    }
    __syncthreads();

    // bulk flush of smem pair buffer
    unsigned nu = s_nu < SCAP ? s_nu : SCAP;
    if (tid == 0 && nu) s_base = atomicAdd(&g_np, nu);
    __syncthreads();
    for (unsigned i = tid; i < nu; i += NTHREADS) {
        unsigned gi = s_base + i;
        if (gi < PAIR_CAP) g_pairs[gi] = s_pairs[i];
    }

    if (tid < TM) {
        int v = scnt[tid];
        if (v) atomicAdd(&cnt[row0 + tid], v);
    }
}

// ---------------- kernel 3: exact fp32 repair of uncertain pairs ------------
__global__ __launch_bounds__(256) void repair_kernel()
{
    int gw = (blockIdx.x * blockDim.x + threadIdx.x) >> 5;
    int lane = threadIdx.x & 31;
    int nwarps = (gridDim.x * blockDim.x) >> 5;
    unsigned np = g_np;
    if (np > PAIR_CAP) np = PAIR_CAP;

    for (unsigned i = gw; i < np; i += nwarps) {
        uint32_t e = g_pairs[i];
        int dir = (int)(e >> 26);
        int row = (int)((e >> 13) & 8191u);
        int col = (int)(e & 8191u);
        const float* ya = dir ? g_yv2 : g_yv1;
        const float* yb = dir ? g_yp1 : g_yp2;
        const float* dg = dir ? g_diag2 : g_diag1;
        int* cnt = dir ? g_cnt2 : g_cnt1;

        const float4* ra = (const float4*)(ya + (size_t)row * C);
        const float4* rb = (const float4*)(yb + (size_t)col * C);
        float s = 0.0f;
        #pragma unroll
        for (int j = 0; j < 2; j++) {
            float4 a = ra[lane + j * 32];
            float4 b = rb[lane + j * 32];
            s = fmaf(a.x, b.x, fmaf(a.y, b.y, fmaf(a.z, b.z, fmaf(a.w, b.w, s))));
        }
        #pragma unroll
        for (int o = 16; o; o >>= 1) s += __shfl_xor_sync(0xffffffffu, s, o);
        if (lane == 0 && s > __ldg(&dg[row])) atomicAdd(&cnt[row], 1);
    }
}

// ---------------- kernel 4: final scalars (parallel, last-block writes) -----
__global__ __launch_bounds__(256) void finalize_kernel(float* __restrict__ out)
{
    int tid = threadIdx.x;
    int gid = blockIdx.x * blockDim.x + tid;
    int stride = gridDim.x * blockDim.x;

    double sd = 0.0, sp = 0.0;
    int r1 = 0, r5 = 0, r10 = 0;
    for (int i = gid; i < N; i += stride) {
        sd += (double)g_diag1[i] + (double)g_diag2[i];
        int c1 = g_cnt1[i], c2 = g_cnt2[i];
        sp += (double)(c1 + c2);
        r1  += (c1 < 1)  + (c2 < 1);
        r5  += (c1 < 5)  + (c2 < 5);
        r10 += (c1 < 10) + (c2 < 10);
    }
    #pragma unroll
    for (int o = 16; o; o >>= 1) {
        sd  += __shfl_xor_sync(0xffffffffu, sd, o);
        sp  += __shfl_xor_sync(0xffffffffu, sp, o);
        r1  += __shfl_xor_sync(0xffffffffu, r1, o);
        r5  += __shfl_xor_sync(0xffffffffu, r5, o);
        r10 += __shfl_xor_sync(0xffffffffu, r10, o);
    }
    __shared__ double s_sd[8], s_sp[8];
    __shared__ int s_r1[8], s_r5[8], s_r10[8];
    int lane = tid & 31, w = tid >> 5;
    if (lane == 0) { s_sd[w] = sd; s_sp[w] = sp; s_r1[w] = r1; s_r5[w] = r5; s_r10[w] = r10; }
    __syncthreads();
    __shared__ unsigned int s_last;
    if (tid == 0) {
        double tsd = 0, tsp = 0; int t1 = 0, t5 = 0, t10 = 0;
        for (int i = 0; i < 8; i++) {
            tsd += s_sd[i]; tsp += s_sp[i];
            t1 += s_r1[i]; t5 += s_r5[i]; t10 += s_r10[i];
        }
        atomicAdd(&g_sd, tsd); atomicAdd(&g_sp, tsp);
        atomicAdd(&g_r1, t1); atomicAdd(&g_r5, t5); atomicAdd(&g_r10, t10);
        __threadfence();
        s_last = atomicAdd(&g_ticket, 1u);
    }
    __syncthreads();
    if (tid == 0 && s_last == gridDim.x - 1) {
        __threadfence();
        double inv2N = 1.0 / (2.0 * (double)N);
        out[0] = (float)(-g_sd * inv2N);
        out[1] = (float)((double)g_r1  * inv2N);
        out[2] = (float)((double)g_r5  * inv2N);
        out[3] = (float)((double)g_r10 * inv2N);
        out[4] = (float)((g_sp + (double)N) * inv2N);
    }
}

// ---------------- launch ------------------------------------------------------
extern "C" void kernel_launch(void* const* d_in, const int* in_sizes, int n_in,
                              void* d_out, int out_size)
{
    const float* v1 = (const float*)d_in[0];
    const float* v2 = (const float*)d_in[1];
    const float* p1 = (const float*)d_in[2];
    const float* p2 = (const float*)d_in[3];
    float* out = (float*)d_out;

    cudaFuncSetAttribute(count_kernel, cudaFuncAttributeMaxDynamicSharedMemorySize, SMEM_BYTES);

    normalize_kernel<<<N, 256>>>(v1, v2, p1, p2);
    dim3 grid(N / TN, N / TM, 2);
    count_kernel<<<grid, NTHREADS, SMEM_BYTES>>>();
    repair_kernel<<<512, 256>>>();
    finalize_kernel<<<32, 256>>>(out);
}

// round 6
// speedup vs baseline: 1.5086x; 1.1009x over previous
#include <cuda_runtime.h>
#include <cuda_fp16.h>
#include <math.h>
#include <stdint.h>

#define N 8192
#define C 256
#define TM 128            // CTA M tile
#define TN 128            // CTA N tile
#define KC 64             // K chunk (64 halves = 128B rows)
#define NCHUNK 4          // K = 256
#define NTHREADS 256
#define STAGE_BYTES 32768 // A 16KB + B 16KB
#define NSTAGE 3
#define SMEM_BYTES (NSTAGE * STAGE_BYTES + 1024)
#define PAIR_CAP (4u * 1024u * 1024u)
#define SCAP 1024

// ---------------- scratch (device globals; no allocation allowed) -----------
__device__ __half g_ah1[(size_t)N * C];    // v1 hi
__device__ __half g_ah2[(size_t)N * C];    // v2 hi
__device__ __half g_bh1[(size_t)N * C];    // p1 hi
__device__ __half g_bh2[(size_t)N * C];    // p2 hi
__device__ float g_iv1[N], g_iv2[N], g_ip1[N], g_ip2[N];      // inv norms
__device__ float g_nlv1[N], g_nlv2[N], g_nlp1[N], g_nlp2[N];  // ||lo|| per row
__device__ float g_diag1[N], g_diag2[N];
__device__ int   g_cnt1[N], g_cnt2[N];
__device__ unsigned int g_np;
__device__ uint32_t g_pairs[PAIR_CAP];
// finalize accumulators
__device__ double g_sd, g_sp;
__device__ int g_r1, g_r5, g_r10;
__device__ unsigned int g_ticket;

// ---------------- helpers ----------------------------------------------------
__device__ __forceinline__ uint32_t smem_u32(const void* p) {
    uint32_t a;
    asm("{ .reg .u64 t; cvta.to.shared.u64 t, %1; cvt.u32.u64 %0, t; }" : "=r"(a) : "l"(p));
    return a;
}
#define SWZ(x) ((x) ^ (((x) >> 3) & 0x70))

__device__ __forceinline__ void cp_async16(uint32_t sa, const void* g) {
    asm volatile("cp.async.cg.shared.global [%0], [%1], 16;" :: "r"(sa), "l"(g));
}
__device__ __forceinline__ void ldsm_x4(uint32_t* r, uint32_t addr) {
    asm volatile("ldmatrix.sync.aligned.m8n8.x4.shared.b16 {%0,%1,%2,%3}, [%4];"
                 : "=r"(r[0]), "=r"(r[1]), "=r"(r[2]), "=r"(r[3]) : "r"(addr));
}
__device__ __forceinline__ void mma16816(float* d, const uint32_t* a, const uint32_t* b) {
    asm volatile("mma.sync.aligned.m16n8k16.row.col.f32.f16.f16.f32 "
                 "{%0,%1,%2,%3}, {%4,%5,%6,%7}, {%8,%9}, {%0,%1,%2,%3};"
                 : "+f"(d[0]), "+f"(d[1]), "+f"(d[2]), "+f"(d[3])
                 : "r"(a[0]), "r"(a[1]), "r"(a[2]), "r"(a[3]), "r"(b[0]), "r"(b[1]));
}

// ---------------- block reduce (256 threads) --------------------------------
__device__ __forceinline__ float blockReduceSum256(float v, float* sred) {
    #pragma unroll
    for (int o = 16; o; o >>= 1) v += __shfl_xor_sync(0xffffffffu, v, o);
    int lane = threadIdx.x & 31, w = threadIdx.x >> 5;
    if (lane == 0) sred[w] = v;
    __syncthreads();
    if (w == 0) {
        v = (lane < 8) ? sred[lane] : 0.0f;
        #pragma unroll
        for (int o = 4; o; o >>= 1) v += __shfl_xor_sync(0xffffffffu, v, o);
        if (lane == 0) sred[0] = v;
    }
    __syncthreads();
    float r = sred[0];
    __syncthreads();
    return r;
}

// ---------------- kernel 1: normalize + hi split + lo-norms + diag ----------
__global__ __launch_bounds__(256) void normalize_kernel(
    const float* __restrict__ v1, const float* __restrict__ v2,
    const float* __restrict__ p1, const float* __restrict__ p2)
{
    __shared__ float sred[8];
    int row = blockIdx.x;
    int t = threadIdx.x;
    size_t off = (size_t)row * C + t;

    float a = v1[off], b = v2[off], c = p1[off], d = p2[off];

    float na = blockReduceSum256(a * a, sred);
    float nb = blockReduceSum256(b * b, sred);
    float nc = blockReduceSum256(c * c, sred);
    float nd = blockReduceSum256(d * d, sred);

    float ia = 1.0f / fmaxf(sqrtf(na), 1e-12f);
    float ib = 1.0f / fmaxf(sqrtf(nb), 1e-12f);
    float ic = 1.0f / fmaxf(sqrtf(nc), 1e-12f);
    float id = 1.0f / fmaxf(sqrtf(nd), 1e-12f);

    float an = a * ia, bn = b * ib, cn = c * ic, dn = d * id;

    __half ha = __float2half_rn(an), hb = __float2half_rn(bn);
    __half hc = __float2half_rn(cn), hd = __float2half_rn(dn);
    g_ah1[off] = ha; g_ah2[off] = hb; g_bh1[off] = hc; g_bh2[off] = hd;

    float la = an - __half2float(ha), lb = bn - __half2float(hb);
    float lc = cn - __half2float(hc), ld = dn - __half2float(hd);

    float sla = blockReduceSum256(la * la, sred);
    float slb = blockReduceSum256(lb * lb, sred);
    float slc = blockReduceSum256(lc * lc, sred);
    float sld = blockReduceSum256(ld * ld, sred);

    float d1 = blockReduceSum256(an * dn, sred);   // v1n . p2n
    float d2 = blockReduceSum256(bn * cn, sred);   // v2n . p1n

    if (t == 0) {
        g_iv1[row] = ia; g_iv2[row] = ib; g_ip1[row] = ic; g_ip2[row] = id;
        g_nlv1[row] = sqrtf(sla); g_nlv2[row] = sqrtf(slb);
        g_nlp1[row] = sqrtf(slc); g_nlp2[row] = sqrtf(sld);
        g_diag1[row] = d1; g_diag2[row] = d2;
        g_cnt1[row] = 0;  g_cnt2[row] = 0;
        if (row == 0) {
            g_np = 0; g_sd = 0.0; g_sp = 0.0;
            g_r1 = 0; g_r5 = 0; g_r10 = 0; g_ticket = 0;
        }
    }
}

// ---------------- kernel 2: hi-only mma.sync GEMM + classify ----------------
// CTA: 128x128, 256 threads (8 warps 2Mx4N), warp tile 64x32, K=256.
// 3-stage combined A+B chunk pipeline (32KB/stage) -> 2 CTAs/SM.
extern __shared__ char dynsmem[];

__global__ void __launch_bounds__(NTHREADS, 2) count_kernel()
{
    __shared__ int scnt[TM];
    __shared__ uint32_t s_pairs[SCAP];
    __shared__ unsigned int s_nu, s_base;

    const __half* __restrict__ A;
    const __half* __restrict__ B;
    const float* __restrict__ diag;
    const float* __restrict__ nla;
    const float* __restrict__ nlb;
    int* cnt;
    if (blockIdx.z == 0) { A = g_ah1; B = g_bh2; diag = g_diag1; nla = g_nlv1; nlb = g_nlp2; cnt = g_cnt1; }
    else                 { A = g_ah2; B = g_bh1; diag = g_diag2; nla = g_nlv2; nlb = g_nlp1; cnt = g_cnt2; }

    int tid = threadIdx.x;
    int wid = tid >> 5;
    int lane = tid & 31;
    int wm = wid >> 2;            // 0..1
    int wn = wid & 3;             // 0..3
    int row0 = blockIdx.y * TM;
    int col0 = blockIdx.x * TN;

    char* al = (char*)((((uintptr_t)dynsmem) + 1023) & ~(uintptr_t)1023);
    uint32_t sbase = smem_u32(al);

    if (tid < TM) scnt[tid] = 0;
    if (tid == 0) s_nu = 0;

    // chunk loader: A 128x128B + B 128x128B into stage s
    auto load_chunk = [&](int c, int s) {
        uint32_t st = sbase + (uint32_t)s * STAGE_BYTES;
        #pragma unroll
        for (int i = 0; i < 4; i++) {            // A: 1024 x 16B
            int idx = tid + i * NTHREADS;
            int r = idx >> 3, kg = idx & 7;
            const __half* g = A + (size_t)(row0 + r) * C + c * KC + kg * 8;
            cp_async16(st + SWZ((uint32_t)(r * 128 + kg * 16)), g);
        }
        #pragma unroll
        for (int i = 0; i < 4; i++) {            // B: 1024 x 16B
            int idx = tid + i * NTHREADS;
            int r = idx >> 3, kg = idx & 7;
            const __half* g = B + (size_t)(col0 + r) * C + c * KC + kg * 8;
            cp_async16(st + 16384u + SWZ((uint32_t)(r * 128 + kg * 16)), g);
        }
        asm volatile("cp.async.commit_group;" ::: "memory");
    };

    float acc[4][4][4];
    #pragma unroll
    for (int mi = 0; mi < 4; mi++)
        #pragma unroll
        for (int n8 = 0; n8 < 4; n8++)
            #pragma unroll
            for (int e = 0; e < 4; e++) acc[mi][n8][e] = 0.0f;

    load_chunk(0, 0);
    load_chunk(1, 1);

    #pragma unroll
    for (int c = 0; c < NCHUNK; c++) {
        if (c + 1 < NCHUNK) asm volatile("cp.async.wait_group 1;" ::: "memory");
        else                asm volatile("cp.async.wait_group 0;" ::: "memory");
        __syncthreads();

        if (c + 2 < NCHUNK) load_chunk(c + 2, (c + 2) % NSTAGE);

        uint32_t stA = sbase + (uint32_t)(c % NSTAGE) * STAGE_BYTES;
        uint32_t stB = stA + 16384u;

        #pragma unroll
        for (int ks = 0; ks < 4; ks++) {
            uint32_t a[4][4], b[2][4];
            int kbA = ks * 32 + (lane >> 4) * 16;
            #pragma unroll
            for (int mi = 0; mi < 4; mi++) {
                int rowA = wm * 64 + mi * 16 + (lane & 15);
                uint32_t ad = stA + (uint32_t)(rowA * 128) +
                              (uint32_t)(kbA ^ ((rowA & 7) << 4));
                ldsm_x4(a[mi], ad);
            }
            int kbB = ks * 32 + ((lane >> 3) & 1) * 16;
            #pragma unroll
            for (int nb = 0; nb < 2; nb++) {
                int rowB = wn * 32 + nb * 16 + (lane & 7) + ((lane >> 4) & 1) * 8;
                uint32_t bd = stB + (uint32_t)(rowB * 128) +
                              (uint32_t)(kbB ^ ((rowB & 7) << 4));
                ldsm_x4(b[nb], bd);
            }
            #pragma unroll
            for (int mi = 0; mi < 4; mi++)
                #pragma unroll
                for (int n8 = 0; n8 < 4; n8++)
                    mma16816(acc[mi][n8], a[mi], &b[n8 >> 1][(n8 & 1) * 2]);
        }
        __syncthreads();
    }

    // ---- epilogue: definite counts + uncertain via per-pair adaptive bound -
    int gid = lane >> 2, tig = lane & 3;
    uint32_t dirbit = (uint32_t)blockIdx.z << 26;

    float bcol[8];
    #pragma unroll
    for (int n8 = 0; n8 < 4; n8++)
        #pragma unroll
        for (int e = 0; e < 2; e++)
            bcol[n8 * 2 + e] = __ldg(&nlb[col0 + wn * 32 + n8 * 8 + tig * 2 + e]);

    #pragma unroll
    for (int mi = 0; mi < 4; mi++) {
        #pragma unroll
        for (int h = 0; h < 2; h++) {
            int lrow = wm * 64 + mi * 16 + gid + h * 8;
            int grow = row0 + lrow;
            float dv = __ldg(&diag[grow]);
            float na = __ldg(&nla[grow]);
            int cc = 0;
            #pragma unroll
            for (int n8 = 0; n8 < 4; n8++) {
                #pragma unroll
                for (int e = 0; e < 2; e++) {
                    float vv = acc[mi][n8][h * 2 + e];
                    int gcol = col0 + wn * 32 + n8 * 8 + tig * 2 + e;
                    float bnd = 0.375f * (na + bcol[n8 * 2 + e]) + 4e-5f;
                    if (gcol != grow) {
                        if (vv > dv + bnd) cc++;
                        else if (vv > dv - bnd) {
                            unsigned idx = atomicAdd(&s_nu, 1u);
                            uint32_t rec = dirbit | ((uint32_t)grow << 13) | (uint32_t)gcol;
                            if (idx < SCAP) s_pairs[idx] = rec;
                            else {
                                unsigned gi = atomicAdd(&g_np, 1u);
                                if (gi < PAIR_CAP) g_pairs[gi] = rec;
                            }
                        }
                    }
                }
            }
            if (cc) atomicAdd(&scnt[lrow], cc);
        }
    }
    __syncthreads();

    // bulk flush of smem pair buffer
    unsigned nu = s_nu < SCAP ? s_nu : SCAP;
    if (tid == 0 && nu) s_base = atomicAdd(&g_np, nu);
    __syncthreads();
    for (unsigned i = tid; i < nu; i += NTHREADS) {
        unsigned gi = s_base + i;
        if (gi < PAIR_CAP) g_pairs[gi] = s_pairs[i];
    }

    if (tid < TM) {
        int v = scnt[tid];
        if (v) atomicAdd(&cnt[row0 + tid], v);
    }
}

// ---------------- kernel 3: exact fp32 repair of uncertain pairs ------------
// Recomputes normalized elements on the fly: (raw * inv_norm) — identical
// rounding to storing normalized fp32 and re-reading it.
__global__ __launch_bounds__(256) void repair_kernel(
    const float* __restrict__ v1, const float* __restrict__ v2,
    const float* __restrict__ p1, const float* __restrict__ p2)
{
    int gw = (blockIdx.x * blockDim.x + threadIdx.x) >> 5;
    int lane = threadIdx.x & 31;
    int nwarps = (gridDim.x * blockDim.x) >> 5;
    unsigned np = g_np;
    if (np > PAIR_CAP) np = PAIR_CAP;

    for (unsigned i = gw; i < np; i += nwarps) {
        uint32_t e = g_pairs[i];
        int dir = (int)(e >> 26);
        int row = (int)((e >> 13) & 8191u);
        int col = (int)(e & 8191u);
        const float* ya = dir ? v2 : v1;
        const float* yb = dir ? p1 : p2;
        const float* iva = dir ? g_iv2 : g_iv1;
        const float* ivb = dir ? g_ip1 : g_ip2;
        const float* dg = dir ? g_diag2 : g_diag1;
        int* cnt = dir ? g_cnt2 : g_cnt1;

        float ia = __ldg(&iva[row]);
        float ib = __ldg(&ivb[col]);
        const float4* ra = (const float4*)(ya + (size_t)row * C);
        const float4* rb = (const float4*)(yb + (size_t)col * C);
        float s = 0.0f;
        #pragma unroll
        for (int j = 0; j < 2; j++) {
            float4 a = ra[lane + j * 32];
            float4 b = rb[lane + j * 32];
            float ax = a.x * ia, ay = a.y * ia, az = a.z * ia, aw = a.w * ia;
            float bx = b.x * ib, by = b.y * ib, bz = b.z * ib, bw = b.w * ib;
            s = fmaf(ax, bx, fmaf(ay, by, fmaf(az, bz, fmaf(aw, bw, s))));
        }
        #pragma unroll
        for (int o = 16; o; o >>= 1) s += __shfl_xor_sync(0xffffffffu, s, o);
        if (lane == 0 && s > __ldg(&dg[row])) atomicAdd(&cnt[row], 1);
    }
}

// ---------------- kernel 4: final scalars (parallel, last-block writes) -----
__global__ __launch_bounds__(256) void finalize_kernel(float* __restrict__ out)
{
    int tid = threadIdx.x;
    int gid = blockIdx.x * blockDim.x + tid;
    int stride = gridDim.x * blockDim.x;

    double sd = 0.0, sp = 0.0;
    int r1 = 0, r5 = 0, r10 = 0;
    for (int i = gid; i < N; i += stride) {
        sd += (double)g_diag1[i] + (double)g_diag2[i];
        int c1 = g_cnt1[i], c2 = g_cnt2[i];
        sp += (double)(c1 + c2);
        r1  += (c1 < 1)  + (c2 < 1);
        r5  += (c1 < 5)  + (c2 < 5);
        r10 += (c1 < 10) + (c2 < 10);
    }
    #pragma unroll
    for (int o = 16; o; o >>= 1) {
        sd  += __shfl_xor_sync(0xffffffffu, sd, o);
        sp  += __shfl_xor_sync(0xffffffffu, sp, o);
        r1  += __shfl_xor_sync(0xffffffffu, r1, o);
        r5  += __shfl_xor_sync(0xffffffffu, r5, o);
        r10 += __shfl_xor_sync(0xffffffffu, r10, o);
    }
    __shared__ double s_sd[8], s_sp[8];
    __shared__ int s_r1[8], s_r5[8], s_r10[8];
    int lane = tid & 31, w = tid >> 5;
    if (lane == 0) { s_sd[w] = sd; s_sp[w] = sp; s_r1[w] = r1; s_r5[w] = r5; s_r10[w] = r10; }
    __syncthreads();
    __shared__ unsigned int s_last;
    if (tid == 0) {
        double tsd = 0, tsp = 0; int t1 = 0, t5 = 0, t10 = 0;
        for (int i = 0; i < 8; i++) {
            tsd += s_sd[i]; tsp += s_sp[i];
            t1 += s_r1[i]; t5 += s_r5[i]; t10 += s_r10[i];
        }
        atomicAdd(&g_sd, tsd); atomicAdd(&g_sp, tsp);
        atomicAdd(&g_r1, t1); atomicAdd(&g_r5, t5); atomicAdd(&g_r10, t10);
        __threadfence();
        s_last = atomicAdd(&g_ticket, 1u);
    }
    __syncthreads();
    if (tid == 0 && s_last == gridDim.x - 1) {
        __threadfence();
        double inv2N = 1.0 / (2.0 * (double)N);
        out[0] = (float)(-g_sd * inv2N);
        out[1] = (float)((double)g_r1  * inv2N);
        out[2] = (float)((double)g_r5  * inv2N);
        out[3] = (float)((double)g_r10 * inv2N);
        out[4] = (float)((g_sp + (double)N) * inv2N);
    }
}

// ---------------- launch ------------------------------------------------------
extern "C" void kernel_launch(void* const* d_in, const int* in_sizes, int n_in,
                              void* d_out, int out_size)
{
    const float* v1 = (const float*)d_in[0];
    const float* v2 = (const float*)d_in[1];
    const float* p1 = (const float*)d_in[2];
    const float* p2 = (const float*)d_in[3];
    float* out = (float*)d_out;

    cudaFuncSetAttribute(count_kernel, cudaFuncAttributeMaxDynamicSharedMemorySize, SMEM_BYTES);

    normalize_kernel<<<N, 256>>>(v1, v2, p1, p2);
    dim3 grid(N / TN, N / TM, 2);
    count_kernel<<<grid, NTHREADS, SMEM_BYTES>>>();
    repair_kernel<<<512, 256>>>(v1, v2, p1, p2);
    finalize_kernel<<<32, 256>>>(out);
}

// round 7
// speedup vs baseline: 1.5943x; 1.0568x over previous
#include <cuda_runtime.h>
#include <cuda_fp16.h>
#include <math.h>
#include <stdint.h>

#define N 8192
#define C 256
#define TM 128            // CTA M tile
#define TN 128            // N subtile
#define NSUB 4            // subtiles per CTA -> 512 N per CTA
#define KC 64             // K chunk (64 halves = 128B rows)
#define NKC 4             // K chunks (K=256)
#define NIT (NSUB * NKC)  // 16 chunk iterations
#define NTHREADS 256
#define A_BYTES 65536     // 128 rows x 256 halves, as 4 swizzled 16KB chunks
#define B_STAGE 16384     // 128 rows x 64 halves
#define B_OFF A_BYTES
#define SMEM_BYTES (A_BYTES + 2 * B_STAGE + 1024)
#define PAIR_CAP (4u * 1024u * 1024u)
#define SCAP 512

// ---------------- scratch (device globals; no allocation allowed) -----------
__device__ __half g_ah1[(size_t)N * C];    // v1 hi
__device__ __half g_ah2[(size_t)N * C];    // v2 hi
__device__ __half g_bh1[(size_t)N * C];    // p1 hi
__device__ __half g_bh2[(size_t)N * C];    // p2 hi
__device__ float g_iv1[N], g_iv2[N], g_ip1[N], g_ip2[N];      // inv norms
__device__ float g_nlv1[N], g_nlv2[N], g_nlp1[N], g_nlp2[N];  // ||lo|| per row
__device__ float g_diag1[N], g_diag2[N];
__device__ int   g_cnt1[N], g_cnt2[N];
__device__ unsigned int g_np;
__device__ uint32_t g_pairs[PAIR_CAP];
// finalize accumulators
__device__ double g_sd, g_sp;
__device__ int g_r1, g_r5, g_r10;
__device__ unsigned int g_ticket;

// ---------------- helpers ----------------------------------------------------
__device__ __forceinline__ uint32_t smem_u32(const void* p) {
    uint32_t a;
    asm("{ .reg .u64 t; cvta.to.shared.u64 t, %1; cvt.u32.u64 %0, t; }" : "=r"(a) : "l"(p));
    return a;
}
#define SWZ(x) ((x) ^ (((x) >> 3) & 0x70))

__device__ __forceinline__ void cp_async16(uint32_t sa, const void* g) {
    asm volatile("cp.async.cg.shared.global [%0], [%1], 16;" :: "r"(sa), "l"(g));
}
__device__ __forceinline__ void ldsm_x4(uint32_t* r, uint32_t addr) {
    asm volatile("ldmatrix.sync.aligned.m8n8.x4.shared.b16 {%0,%1,%2,%3}, [%4];"
                 : "=r"(r[0]), "=r"(r[1]), "=r"(r[2]), "=r"(r[3]) : "r"(addr));
}
__device__ __forceinline__ void mma16816(float* d, const uint32_t* a, const uint32_t* b) {
    asm volatile("mma.sync.aligned.m16n8k16.row.col.f32.f16.f16.f32 "
                 "{%0,%1,%2,%3}, {%4,%5,%6,%7}, {%8,%9}, {%0,%1,%2,%3};"
                 : "+f"(d[0]), "+f"(d[1]), "+f"(d[2]), "+f"(d[3])
                 : "r"(a[0]), "r"(a[1]), "r"(a[2]), "r"(a[3]), "r"(b[0]), "r"(b[1]));
}

// ---------------- block reduce (256 threads) --------------------------------
__device__ __forceinline__ float blockReduceSum256(float v, float* sred) {
    #pragma unroll
    for (int o = 16; o; o >>= 1) v += __shfl_xor_sync(0xffffffffu, v, o);
    int lane = threadIdx.x & 31, w = threadIdx.x >> 5;
    if (lane == 0) sred[w] = v;
    __syncthreads();
    if (w == 0) {
        v = (lane < 8) ? sred[lane] : 0.0f;
        #pragma unroll
        for (int o = 4; o; o >>= 1) v += __shfl_xor_sync(0xffffffffu, v, o);
        if (lane == 0) sred[0] = v;
    }
    __syncthreads();
    float r = sred[0];
    __syncthreads();
    return r;
}

// ---------------- kernel 1: normalize + hi split + lo-norms + diag ----------
__global__ __launch_bounds__(256) void normalize_kernel(
    const float* __restrict__ v1, const float* __restrict__ v2,
    const float* __restrict__ p1, const float* __restrict__ p2)
{
    __shared__ float sred[8];
    int row = blockIdx.x;
    int t = threadIdx.x;
    size_t off = (size_t)row * C + t;

    float a = v1[off], b = v2[off], c = p1[off], d = p2[off];

    float na = blockReduceSum256(a * a, sred);
    float nb = blockReduceSum256(b * b, sred);
    float nc = blockReduceSum256(c * c, sred);
    float nd = blockReduceSum256(d * d, sred);

    float ia = 1.0f / fmaxf(sqrtf(na), 1e-12f);
    float ib = 1.0f / fmaxf(sqrtf(nb), 1e-12f);
    float ic = 1.0f / fmaxf(sqrtf(nc), 1e-12f);
    float id = 1.0f / fmaxf(sqrtf(nd), 1e-12f);

    float an = a * ia, bn = b * ib, cn = c * ic, dn = d * id;

    __half ha = __float2half_rn(an), hb = __float2half_rn(bn);
    __half hc = __float2half_rn(cn), hd = __float2half_rn(dn);
    g_ah1[off] = ha; g_ah2[off] = hb; g_bh1[off] = hc; g_bh2[off] = hd;

    float la = an - __half2float(ha), lb = bn - __half2float(hb);
    float lc = cn - __half2float(hc), ld = dn - __half2float(hd);

    float sla = blockReduceSum256(la * la, sred);
    float slb = blockReduceSum256(lb * lb, sred);
    float slc = blockReduceSum256(lc * lc, sred);
    float sld = blockReduceSum256(ld * ld, sred);

    float d1 = blockReduceSum256(an * dn, sred);   // v1n . p2n
    float d2 = blockReduceSum256(bn * cn, sred);   // v2n . p1n

    if (t == 0) {
        g_iv1[row] = ia; g_iv2[row] = ib; g_ip1[row] = ic; g_ip2[row] = id;
        g_nlv1[row] = sqrtf(sla); g_nlv2[row] = sqrtf(slb);
        g_nlp1[row] = sqrtf(slc); g_nlp2[row] = sqrtf(sld);
        g_diag1[row] = d1; g_diag2[row] = d2;
        g_cnt1[row] = 0;  g_cnt2[row] = 0;
        if (row == 0) {
            g_np = 0; g_sd = 0.0; g_sp = 0.0;
            g_r1 = 0; g_r5 = 0; g_r10 = 0; g_ticket = 0;
        }
    }
}

// ---------------- kernel 2: A-resident mma.sync GEMM + classify -------------
// CTA: 128(M) x 512(N) as 4 subtiles of 128, 256 threads (8 warps 2Mx4N),
// warp tile 64x32, K=256. A (64KB) loaded once; B streamed 2-stage (16KB).
extern __shared__ char dynsmem[];

__global__ void __launch_bounds__(NTHREADS, 2) count_kernel()
{
    __shared__ int scnt[TM];
    __shared__ uint32_t s_pairs[SCAP];
    __shared__ unsigned int s_nu, s_base;

    const __half* __restrict__ A;
    const __half* __restrict__ B;
    const float* __restrict__ diag;
    const float* __restrict__ nla;
    const float* __restrict__ nlb;
    int* cnt;
    if (blockIdx.z == 0) { A = g_ah1; B = g_bh2; diag = g_diag1; nla = g_nlv1; nlb = g_nlp2; cnt = g_cnt1; }
    else                 { A = g_ah2; B = g_bh1; diag = g_diag2; nla = g_nlv2; nlb = g_nlp1; cnt = g_cnt2; }

    int tid = threadIdx.x;
    int wid = tid >> 5;
    int lane = tid & 31;
    int wm = wid >> 2;            // 0..1
    int wn = wid & 3;             // 0..3
    int row0 = blockIdx.y * TM;
    int col0 = blockIdx.x * (TN * NSUB);

    char* al = (char*)((((uintptr_t)dynsmem) + 1023) & ~(uintptr_t)1023);
    uint32_t sbase = smem_u32(al);

    if (tid < TM) scnt[tid] = 0;
    if (tid == 0) s_nu = 0;

    // A: all 4 K-chunks (one commit group). 128 rows x 64 halves per chunk.
    #pragma unroll
    for (int c = 0; c < NKC; c++) {
        #pragma unroll
        for (int i = 0; i < 4; i++) {          // 1024 x 16B
            int idx = tid + i * NTHREADS;
            int r = idx >> 3, kg = idx & 7;
            const __half* g = A + (size_t)(row0 + r) * C + c * KC + kg * 8;
            cp_async16(sbase + (uint32_t)c * 16384u + SWZ((uint32_t)(r * 128 + kg * 16)), g);
        }
    }
    asm volatile("cp.async.commit_group;" ::: "memory");

    // B chunk loader: global chunk g = nsub*4 + kc, into stage
    auto load_B = [&](int g, int stage) {
        int nsub = g >> 2, kc = g & 3;
        uint32_t st = sbase + B_OFF + (uint32_t)stage * B_STAGE;
        #pragma unroll
        for (int i = 0; i < 4; i++) {          // 1024 x 16B
            int idx = tid + i * NTHREADS;
            int r = idx >> 3, kg = idx & 7;
            const __half* gp = B + (size_t)(col0 + nsub * TN + r) * C + kc * KC + kg * 8;
            cp_async16(st + SWZ((uint32_t)(r * 128 + kg * 16)), gp);
        }
        asm volatile("cp.async.commit_group;" ::: "memory");
    };

    load_B(0, 0);
    load_B(1, 1);

    // per-row epilogue thresholds (8 rows per thread, fixed across subtiles)
    int gid = lane >> 2, tig = lane & 3;
    float thrHi[8], thrLo[8];
    #pragma unroll
    for (int mi = 0; mi < 4; mi++)
        #pragma unroll
        for (int h = 0; h < 2; h++) {
            int grow = row0 + wm * 64 + mi * 16 + gid + h * 8;
            float dv = __ldg(&diag[grow]);
            float na = __ldg(&nla[grow]);
            thrHi[mi * 2 + h] = dv + 0.375f * na + 4e-5f;
            thrLo[mi * 2 + h] = dv - 0.375f * na - 4e-5f;
        }
    uint32_t dirbit = (uint32_t)blockIdx.z << 26;

    float acc[4][4][4];
    #pragma unroll
    for (int mi = 0; mi < 4; mi++)
        #pragma unroll
        for (int n8 = 0; n8 < 4; n8++)
            #pragma unroll
            for (int e = 0; e < 4; e++) acc[mi][n8][e] = 0.0f;

    #pragma unroll 1
    for (int it = 0; it < NIT; it++) {
        if (it < NIT - 1) asm volatile("cp.async.wait_group 1;" ::: "memory");
        else              asm volatile("cp.async.wait_group 0;" ::: "memory");
        __syncthreads();

        uint32_t stA = sbase + (uint32_t)(it & 3) * 16384u;
        uint32_t stB = sbase + B_OFF + (uint32_t)(it & 1) * B_STAGE;

        #pragma unroll
        for (int ks = 0; ks < 4; ks++) {
            uint32_t a[4][4], b[2][4];
            int kbA = ks * 32 + (lane >> 4) * 16;
            #pragma unroll
            for (int mi = 0; mi < 4; mi++) {
                int rowA = wm * 64 + mi * 16 + (lane & 15);
                uint32_t ad = stA + (uint32_t)(rowA * 128) +
                              (uint32_t)(kbA ^ ((rowA & 7) << 4));
                ldsm_x4(a[mi], ad);
            }
            int kbB = ks * 32 + ((lane >> 3) & 1) * 16;
            #pragma unroll
            for (int nb = 0; nb < 2; nb++) {
                int rowB = wn * 32 + nb * 16 + (lane & 7) + ((lane >> 4) & 1) * 8;
                uint32_t bd = stB + (uint32_t)(rowB * 128) +
                              (uint32_t)(kbB ^ ((rowB & 7) << 4));
                ldsm_x4(b[nb], bd);
            }
            #pragma unroll
            for (int mi = 0; mi < 4; mi++)
                #pragma unroll
                for (int n8 = 0; n8 < 4; n8++)
                    mma16816(acc[mi][n8], a[mi], &b[n8 >> 1][(n8 & 1) * 2]);
        }
        __syncthreads();                       // all reads of stB done

        if (it + 2 < NIT) load_B(it + 2, it & 1);

        if ((it & 3) == 3) {
            // ---- epilogue for subtile nsub ----
            int nsub = it >> 2;
            int cbase = col0 + nsub * TN + wn * 32;
            float bcol[8];
            #pragma unroll
            for (int n8 = 0; n8 < 4; n8++)
                #pragma unroll
                for (int e = 0; e < 2; e++)
                    bcol[n8 * 2 + e] = 0.375f * __ldg(&nlb[cbase + n8 * 8 + tig * 2 + e]);

            #pragma unroll
            for (int mi = 0; mi < 4; mi++) {
                #pragma unroll
                for (int h = 0; h < 2; h++) {
                    int lrow = wm * 64 + mi * 16 + gid + h * 8;
                    int grow = row0 + lrow;
                    float hi = thrHi[mi * 2 + h], lo = thrLo[mi * 2 + h];
                    int cc = 0;
                    #pragma unroll
                    for (int n8 = 0; n8 < 4; n8++) {
                        #pragma unroll
                        for (int e = 0; e < 2; e++) {
                            float vv = acc[mi][n8][h * 2 + e];
                            float t = bcol[n8 * 2 + e];
                            int gcol = cbase + n8 * 8 + tig * 2 + e;
                            if (gcol != grow) {
                                if (vv - t > hi) cc++;
                                else if (vv + t > lo) {
                                    unsigned idx = atomicAdd(&s_nu, 1u);
                                    uint32_t rec = dirbit | ((uint32_t)grow << 13) | (uint32_t)gcol;
                                    if (idx < SCAP) s_pairs[idx] = rec;
                                    else {
                                        unsigned gi = atomicAdd(&g_np, 1u);
                                        if (gi < PAIR_CAP) g_pairs[gi] = rec;
                                    }
                                }
                            }
                            acc[mi][n8][h * 2 + e] = 0.0f;
                        }
                    }
                    if (cc) atomicAdd(&scnt[lrow], cc);
                }
            }
        }
    }

    __syncthreads();
    // bulk flush of smem pair buffer
    unsigned nu = s_nu < SCAP ? s_nu : SCAP;
    if (tid == 0 && nu) s_base = atomicAdd(&g_np, nu);
    __syncthreads();
    for (unsigned i = tid; i < nu; i += NTHREADS) {
        unsigned gi = s_base + i;
        if (gi < PAIR_CAP) g_pairs[gi] = s_pairs[i];
    }

    if (tid < TM) {
        int v = scnt[tid];
        if (v) atomicAdd(&cnt[row0 + tid], v);
    }
}

// ---------------- kernel 3: exact fp32 repair of uncertain pairs ------------
__global__ __launch_bounds__(256) void repair_kernel(
    const float* __restrict__ v1, const float* __restrict__ v2,
    const float* __restrict__ p1, const float* __restrict__ p2)
{
    int gw = (blockIdx.x * blockDim.x + threadIdx.x) >> 5;
    int lane = threadIdx.x & 31;
    int nwarps = (gridDim.x * blockDim.x) >> 5;
    unsigned np = g_np;
    if (np > PAIR_CAP) np = PAIR_CAP;

    for (unsigned i = gw; i < np; i += nwarps) {
        uint32_t e = g_pairs[i];
        int dir = (int)(e >> 26);
        int row = (int)((e >> 13) & 8191u);
        int col = (int)(e & 8191u);
        const float* ya = dir ? v2 : v1;
        const float* yb = dir ? p1 : p2;
        const float* iva = dir ? g_iv2 : g_iv1;
        const float* ivb = dir ? g_ip1 : g_ip2;
        const float* dg = dir ? g_diag2 : g_diag1;
        int* cnt = dir ? g_cnt2 : g_cnt1;

        float ia = __ldg(&iva[row]);
        float ib = __ldg(&ivb[col]);
        const float4* ra = (const float4*)(ya + (size_t)row * C);
        const float4* rb = (const float4*)(yb + (size_t)col * C);
        float s = 0.0f;
        #pragma unroll
        for (int j = 0; j < 2; j++) {
            float4 a = ra[lane + j * 32];
            float4 b = rb[lane + j * 32];
            float ax = a.x * ia, ay = a.y * ia, az = a.z * ia, aw = a.w * ia;
            float bx = b.x * ib, by = b.y * ib, bz = b.z * ib, bw = b.w * ib;
            s = fmaf(ax, bx, fmaf(ay, by, fmaf(az, bz, fmaf(aw, bw, s))));
        }
        #pragma unroll
        for (int o = 16; o; o >>= 1) s += __shfl_xor_sync(0xffffffffu, s, o);
        if (lane == 0 && s > __ldg(&dg[row])) atomicAdd(&cnt[row], 1);
    }
}

// ---------------- kernel 4: final scalars (parallel, last-block writes) -----
__global__ __launch_bounds__(256) void finalize_kernel(float* __restrict__ out)
{
    int tid = threadIdx.x;
    int gid = blockIdx.x * blockDim.x + tid;
    int stride = gridDim.x * blockDim.x;

    double sd = 0.0, sp = 0.0;
    int r1 = 0, r5 = 0, r10 = 0;
    for (int i = gid; i < N; i += stride) {
        sd += (double)g_diag1[i] + (double)g_diag2[i];
        int c1 = g_cnt1[i], c2 = g_cnt2[i];
        sp += (double)(c1 + c2);
        r1  += (c1 < 1)  + (c2 < 1);
        r5  += (c1 < 5)  + (c2 < 5);
        r10 += (c1 < 10) + (c2 < 10);
    }
    #pragma unroll
    for (int o = 16; o; o >>= 1) {
        sd  += __shfl_xor_sync(0xffffffffu, sd, o);
        sp  += __shfl_xor_sync(0xffffffffu, sp, o);
        r1  += __shfl_xor_sync(0xffffffffu, r1, o);
        r5  += __shfl_xor_sync(0xffffffffu, r5, o);
        r10 += __shfl_xor_sync(0xffffffffu, r10, o);
    }
    __shared__ double s_sd[8], s_sp[8];
    __shared__ int s_r1[8], s_r5[8], s_r10[8];
    int lane = tid & 31, w = tid >> 5;
    if (lane == 0) { s_sd[w] = sd; s_sp[w] = sp; s_r1[w] = r1; s_r5[w] = r5; s_r10[w] = r10; }
    __syncthreads();
    __shared__ unsigned int s_last;
    if (tid == 0) {
        double tsd = 0, tsp = 0; int t1 = 0, t5 = 0, t10 = 0;
        for (int i = 0; i < 8; i++) {
            tsd += s_sd[i]; tsp += s_sp[i];
            t1 += s_r1[i]; t5 += s_r5[i]; t10 += s_r10[i];
        }
        atomicAdd(&g_sd, tsd); atomicAdd(&g_sp, tsp);
        atomicAdd(&g_r1, t1); atomicAdd(&g_r5, t5); atomicAdd(&g_r10, t10);
        __threadfence();
        s_last = atomicAdd(&g_ticket, 1u);
    }
    __syncthreads();
    if (tid == 0 && s_last == gridDim.x - 1) {
        __threadfence();
        double inv2N = 1.0 / (2.0 * (double)N);
        out[0] = (float)(-g_sd * inv2N);
        out[1] = (float)((double)g_r1  * inv2N);
        out[2] = (float)((double)g_r5  * inv2N);
        out[3] = (float)((double)g_r10 * inv2N);
        out[4] = (float)((g_sp + (double)N) * inv2N);
    }
}

// ---------------- launch ------------------------------------------------------
extern "C" void kernel_launch(void* const* d_in, const int* in_sizes, int n_in,
                              void* d_out, int out_size)
{
    const float* v1 = (const float*)d_in[0];
    const float* v2 = (const float*)d_in[1];
    const float* p1 = (const float*)d_in[2];
    const float* p2 = (const float*)d_in[3];
    float* out = (float*)d_out;

    cudaFuncSetAttribute(count_kernel, cudaFuncAttributeMaxDynamicSharedMemorySize, SMEM_BYTES);

    normalize_kernel<<<N, 256>>>(v1, v2, p1, p2);
    dim3 grid(N / (TN * NSUB), N / TM, 2);
    count_kernel<<<grid, NTHREADS, SMEM_BYTES>>>();
    repair_kernel<<<512, 256>>>(v1, v2, p1, p2);
    finalize_kernel<<<32, 256>>>(out);
}